// round 3
// baseline (speedup 1.0000x reference)
#include <cuda_runtime.h>

#define NN 50000
#define EE 800000
#define HH 128
#define LL 3
#define GG 64
#define BN_EPS 1e-5f

// ---------------- scratch (device globals; no allocation allowed) ----------------
__device__ __align__(16) float g_h0[NN * HH];
__device__ __align__(16) float g_h1[NN * HH];
__device__ __align__(16) float g_agg[NN * HH];
__device__ __align__(16) float g_y[NN * HH];
__device__ __align__(16) float g_Wt[LL * 2 * HH * HH];   // [l][k(0..255)][o] pre-transposed
__device__ int   g_rowptr[NN + 1];
__device__ int   g_colidx[EE];
__device__ int   g_cnt[NN];
__device__ float g_invdeg[NN];
__device__ __align__(16) float g_sum[HH];
__device__ __align__(16) float g_sumsq[HH];
__device__ __align__(16) float g_coefA[HH];
__device__ __align__(16) float g_coefB[HH];
__device__ float g_pool[GG];

// ---------------- helpers ----------------
__device__ __forceinline__ const float* sel_h(const float* x, int s) {
    return (s == 0) ? x : ((s == 1) ? g_h0 : g_h1);
}

// ---------------- setup kernels ----------------
__global__ void zero_init_kernel() {
    int i = blockIdx.x * blockDim.x + threadIdx.x;
    if (i < NN) g_cnt[i] = 0;
    if (i < GG) g_pool[i] = 0.f;
}

__global__ void count_kernel(const int* __restrict__ dst) {
    int i = blockIdx.x * blockDim.x + threadIdx.x;
    if (i < EE) atomicAdd(&g_cnt[dst[i]], 1);
}

// single-block exclusive scan over g_cnt -> g_rowptr; also invdeg; resets g_cnt
__global__ void scan_kernel() {
    __shared__ int s[1024];
    const int tid = threadIdx.x;
    const int CH = (NN + 1023) / 1024;      // 49
    int st = tid * CH;
    int en = st + CH; if (en > NN) en = NN;
    int loc = 0;
    for (int i = st; i < en; i++) loc += g_cnt[i];
    s[tid] = loc;
    __syncthreads();
    for (int off = 1; off < 1024; off <<= 1) {
        int v = 0;
        if (tid >= off) v = s[tid - off];
        __syncthreads();
        if (tid >= off) s[tid] += v;
        __syncthreads();
    }
    int run = (tid == 0) ? 0 : s[tid - 1];
    for (int i = st; i < en; i++) {
        int c = g_cnt[i];
        g_rowptr[i] = run;
        run += c;
        g_invdeg[i] = 1.0f / (float)(c > 1 ? c : 1);
        g_cnt[i] = 0;
    }
    if (tid == 0) g_rowptr[NN] = EE;
}

__global__ void fill_kernel(const int* __restrict__ src,
                            const int* __restrict__ dst) {
    int i = blockIdx.x * blockDim.x + threadIdx.x;
    if (i >= EE) return;
    int d = dst[i];
    int pos = g_rowptr[d] + atomicAdd(&g_cnt[d], 1);
    g_colidx[pos] = src[i];
}

// pre-transpose both weight matrices of all layers into [l][k][o]
__global__ void transW_kernel(const float* __restrict__ wl,
                              const float* __restrict__ wr) {
    int idx = blockIdx.x * blockDim.x + threadIdx.x;
    if (idx >= LL * 2 * HH * HH) return;
    int l = idx / (2 * HH * HH);
    int rem = idx % (2 * HH * HH);
    int k = rem / HH;
    int o = rem % HH;
    float v = (k < HH) ? wl[(l * HH + o) * HH + k]
                       : wr[(l * HH + o) * HH + (k - HH)];
    g_Wt[idx] = v;
}

// ---------------- per-layer kernels ----------------
// mean aggregation, CSR, warp per node, float4 per lane
__global__ void agg_kernel(const float* __restrict__ x, int sel) {
    int t = blockIdx.x * blockDim.x + threadIdx.x;
    int node = t >> 5;
    int lane = t & 31;
    if (node >= NN) return;
    const float4* h4 = (const float4*)sel_h(x, sel);
    float4 acc = make_float4(0.f, 0.f, 0.f, 0.f);
    int e0 = g_rowptr[node];
    int e1 = g_rowptr[node + 1];
    for (int j = e0; j < e1; j++) {
        int s = g_colidx[j];
        float4 v = h4[s * 32 + lane];
        acc.x += v.x; acc.y += v.y; acc.z += v.z; acc.w += v.w;
    }
    float inv = g_invdeg[node];
    acc.x *= inv; acc.y *= inv; acc.z *= inv; acc.w *= inv;
    ((float4*)g_agg)[node * 32 + lane] = acc;
}

__global__ void zero_bn_kernel() {
    int c = threadIdx.x;
    g_sum[c] = 0.f;
    g_sumsq[c] = 0.f;
}

// y = relu(agg @ Wl^T + bl + h @ Wr^T) fused with column sum/sumsq for BN.
// 128x128 tile / 256 threads / 8x8 per thread; K=256 (agg|h concat), 16 chunks.
__global__ void gemm_kernel(const float* __restrict__ x, int sel,
                            const float* __restrict__ bias, int layer) {
    __shared__ float As[16 * 128];   // A tile, transposed: As[kk][row]
    __shared__ float Bs[16 * 128];   // W tile: Bs[kk][out]
    __shared__ float ssum[128];
    __shared__ float ssq[128];

    const int tid = threadIdx.x;
    const int tx = tid & 15;
    const int ty = tid >> 4;
    const int row0 = blockIdx.x * 128;

    const float* hin = sel_h(x, sel);

    float acc[8][8];
    {
        float bc[8];
        #pragma unroll
        for (int j = 0; j < 4; j++) {
            bc[j]     = bias[tx * 4 + j];
            bc[4 + j] = bias[64 + tx * 4 + j];
        }
        #pragma unroll
        for (int i = 0; i < 8; i++)
            #pragma unroll
            for (int j = 0; j < 8; j++) acc[i][j] = bc[j];
    }

    for (int chunk = 0; chunk < 16; chunk++) {
        // stage W tile: 16 k-rows x 128 outs (conflict-free float4 copy)
        {
            const float4* w4 = (const float4*)(g_Wt + (layer * 256 + chunk * 16) * HH);
            float4* bs4 = (float4*)Bs;
            #pragma unroll
            for (int i = tid; i < 512; i += 256) bs4[i] = w4[i];
        }
        // stage A tile: 128 rows x 16 k, transposed to As[kk][r]
        {
            const float4* src4 = (const float4*)((chunk < 8) ? g_agg : hin);
            const int cseg = (chunk & 7) * 4;
            #pragma unroll
            for (int i = tid; i < 512; i += 256) {
                int r = i >> 2, seg = i & 3;
                int row = row0 + r;
                float4 v = make_float4(0.f, 0.f, 0.f, 0.f);
                if (row < NN) v = src4[row * 32 + cseg + seg];
                As[(seg * 4 + 0) * 128 + r] = v.x;
                As[(seg * 4 + 1) * 128 + r] = v.y;
                As[(seg * 4 + 2) * 128 + r] = v.z;
                As[(seg * 4 + 3) * 128 + r] = v.w;
            }
        }
        __syncthreads();
        #pragma unroll
        for (int kk = 0; kk < 16; kk++) {
            float4 a0 = *(const float4*)&As[kk * 128 + ty * 4];
            float4 a1 = *(const float4*)&As[kk * 128 + 64 + ty * 4];
            float4 b0 = *(const float4*)&Bs[kk * 128 + tx * 4];
            float4 b1 = *(const float4*)&Bs[kk * 128 + 64 + tx * 4];
            float a[8] = {a0.x, a0.y, a0.z, a0.w, a1.x, a1.y, a1.z, a1.w};
            float b[8] = {b0.x, b0.y, b0.z, b0.w, b1.x, b1.y, b1.z, b1.w};
            #pragma unroll
            for (int i = 0; i < 8; i++)
                #pragma unroll
                for (int j = 0; j < 8; j++)
                    acc[i][j] = fmaf(a[i], b[j], acc[i][j]);
        }
        __syncthreads();
    }

    // epilogue: relu, store, BN column sums
    float csum[8], csq[8];
    #pragma unroll
    for (int j = 0; j < 8; j++) { csum[j] = 0.f; csq[j] = 0.f; }
    #pragma unroll
    for (int i = 0; i < 8; i++) {
        int r = row0 + ((i < 4) ? (ty * 4 + i) : (64 + ty * 4 + i - 4));
        if (r < NN) {
            float v[8];
            #pragma unroll
            for (int j = 0; j < 8; j++) {
                v[j] = fmaxf(acc[i][j], 0.f);
                csum[j] += v[j];
                csq[j]  += v[j] * v[j];
            }
            float4* y4 = (float4*)(g_y + r * HH);
            y4[tx]      = make_float4(v[0], v[1], v[2], v[3]);
            y4[16 + tx] = make_float4(v[4], v[5], v[6], v[7]);
        }
    }
    if (tid < 128) { ssum[tid] = 0.f; ssq[tid] = 0.f; }
    __syncthreads();
    #pragma unroll
    for (int j = 0; j < 4; j++) {
        atomicAdd(&ssum[tx * 4 + j],      csum[j]);
        atomicAdd(&ssq[tx * 4 + j],       csq[j]);
        atomicAdd(&ssum[64 + tx * 4 + j], csum[4 + j]);
        atomicAdd(&ssq[64 + tx * 4 + j],  csq[4 + j]);
    }
    __syncthreads();
    if (tid < 128) {
        atomicAdd(&g_sum[tid],   ssum[tid]);
        atomicAdd(&g_sumsq[tid], ssq[tid]);
    }
}

__global__ void bn_finalize_kernel(const float* __restrict__ gamma,
                                   const float* __restrict__ beta) {
    int c = threadIdx.x;
    float mean = g_sum[c] / (float)NN;
    float var  = g_sumsq[c] / (float)NN - mean * mean;
    float a = gamma[c] * rsqrtf(var + BN_EPS);
    g_coefA[c] = a;
    g_coefB[c] = beta[c] - mean * a;
}

__global__ void normalize_kernel(int outsel) {
    int i = blockIdx.x * blockDim.x + threadIdx.x;
    if (i >= NN * 32) return;
    int c = i & 31;
    float4 a = ((const float4*)g_coefA)[c];
    float4 b = ((const float4*)g_coefB)[c];
    float4 v = ((const float4*)g_y)[i];
    float4 o = make_float4(fmaf(a.x, v.x, b.x), fmaf(a.y, v.y, b.y),
                           fmaf(a.z, v.z, b.z), fmaf(a.w, v.w, b.w));
    float4* hout = (float4*)((outsel == 0) ? g_h0 : g_h1);
    hout[i] = o;
}

// per-node dot with fc_w, atomic into per-graph bins
__global__ void pool_kernel(const int* __restrict__ batch,
                            const float* __restrict__ fcw) {
    int t = blockIdx.x * blockDim.x + threadIdx.x;
    int node = t >> 5;
    int lane = t & 31;
    if (node >= NN) return;
    float4 v = ((const float4*)g_h0)[node * 32 + lane];
    float4 w = ((const float4*)fcw)[lane];
    float s = v.x * w.x + v.y * w.y + v.z * w.z + v.w * w.w;
    #pragma unroll
    for (int off = 16; off; off >>= 1) s += __shfl_down_sync(0xffffffffu, s, off);
    if (lane == 0) atomicAdd(&g_pool[batch[node]], s);
}

__global__ void final_kernel(const float* __restrict__ fcb, float* __restrict__ out) {
    int g = threadIdx.x;
    if (g < GG) {
        float z = g_pool[g] + fcb[0];
        out[g] = 1.0f / (1.0f + expf(-z));
    }
}

// ---------------- launch ----------------
extern "C" void kernel_launch(void* const* d_in, const int* in_sizes, int n_in,
                              void* d_out, int out_size) {
    const float* x       = (const float*)d_in[0];
    const int*   ei      = (const int*)d_in[1];     // int32 (JAX default x64 disabled)
    const int*   src     = ei;
    const int*   dst     = ei + EE;
    const int*   batch   = (const int*)d_in[3];     // int32
    const float* lin_l_w = (const float*)d_in[4];
    const float* lin_l_b = (const float*)d_in[5];
    const float* lin_r_w = (const float*)d_in[6];
    const float* gamma   = (const float*)d_in[7];
    const float* beta    = (const float*)d_in[8];
    const float* fcw     = (const float*)d_in[9];
    const float* fcb     = (const float*)d_in[10];
    float*       out     = (float*)d_out;

    zero_init_kernel<<<(NN + 255) / 256, 256>>>();
    count_kernel<<<(EE + 255) / 256, 256>>>(dst);
    scan_kernel<<<1, 1024>>>();
    fill_kernel<<<(EE + 255) / 256, 256>>>(src, dst);
    transW_kernel<<<(LL * 2 * HH * HH + 255) / 256, 256>>>(lin_l_w, lin_r_w);

    for (int l = 0; l < LL; l++) {
        int sel    = (l == 0) ? 0 : ((l == 1) ? 1 : 2);   // x, g_h0, g_h1
        int outsel = (l == 0) ? 0 : ((l == 1) ? 1 : 0);   // g_h0, g_h1, g_h0
        agg_kernel<<<(NN * 32 + 255) / 256, 256>>>(x, sel);
        zero_bn_kernel<<<1, 128>>>();
        gemm_kernel<<<(NN + 127) / 128, 256>>>(x, sel, lin_l_b + l * HH, l);
        bn_finalize_kernel<<<1, 128>>>(gamma + l * HH, beta + l * HH);
        normalize_kernel<<<(NN * 32 + 255) / 256, 256>>>(outsel);
    }

    pool_kernel<<<(NN * 32 + 255) / 256, 256>>>(batch, fcw);
    final_kernel<<<1, 64>>>(fcb, out);
}

// round 4
// speedup vs baseline: 1.1417x; 1.1417x over previous
#include <cuda_runtime.h>

#define NN 50000
#define EE 800000
#define HH 128
#define LL 3
#define GG 64
#define BN_EPS 1e-5f

// ---------------- scratch (device globals) ----------------
__device__ __align__(16) float g_y0[NN * HH];
__device__ __align__(16) float g_y1[NN * HH];
__device__ __align__(16) float g_agg[NN * HH];
__device__ __align__(16) float g_Wt[LL * 2 * HH * HH];   // [l][k(0..255)][o] pre-transposed
__device__ __align__(16) float g_Ws[2 * HH * HH];        // affine-folded weights, current layer
__device__ __align__(16) float g_bias[HH];               // folded bias, current layer
__device__ int   g_rowptr[NN + 1];
__device__ int   g_colidx[EE];
__device__ int   g_cnt[NN];
__device__ float g_invdeg[NN];
__device__ __align__(16) float g_sum[HH];
__device__ __align__(16) float g_sumsq[HH];
__device__ __align__(16) float g_coefA[HH];
__device__ __align__(16) float g_coefB[HH];
__device__ __align__(16) float g_fcs[HH];
__device__ float g_c0;
__device__ float g_pool[GG];

// ---------------- helpers ----------------
__device__ __forceinline__ const float* sel_h(const float* x, int s) {
    return (s == 0) ? x : ((s == 1) ? g_y0 : g_y1);
}

// packed dual-FMA: d.lo += a.lo*b.lo ; d.hi += a.hi*b.hi  (2x fp32 rate on sm_103a)
__device__ __forceinline__ void ffma2(float2& d, const float2& a, const float2& b) {
    asm("fma.rn.f32x2 %0, %1, %2, %0;"
        : "+l"(reinterpret_cast<unsigned long long&>(d))
        : "l"(reinterpret_cast<const unsigned long long&>(a)),
          "l"(reinterpret_cast<const unsigned long long&>(b)));
}

// ---------------- setup kernels ----------------
__global__ void zero_init_kernel() {
    int i = blockIdx.x * blockDim.x + threadIdx.x;
    if (i < NN) g_cnt[i] = 0;
    if (i < GG) g_pool[i] = 0.f;
    if (i < HH) { g_coefA[i] = 1.f; g_coefB[i] = 0.f; }   // identity affine for layer 0
}

__global__ void count_kernel(const int* __restrict__ dst) {
    int i = blockIdx.x * blockDim.x + threadIdx.x;
    if (i < EE) atomicAdd(&g_cnt[dst[i]], 1);
}

__global__ void scan_kernel() {
    __shared__ int s[1024];
    const int tid = threadIdx.x;
    const int CH = (NN + 1023) / 1024;
    int st = tid * CH;
    int en = st + CH; if (en > NN) en = NN;
    int loc = 0;
    for (int i = st; i < en; i++) loc += g_cnt[i];
    s[tid] = loc;
    __syncthreads();
    for (int off = 1; off < 1024; off <<= 1) {
        int v = 0;
        if (tid >= off) v = s[tid - off];
        __syncthreads();
        if (tid >= off) s[tid] += v;
        __syncthreads();
    }
    int run = (tid == 0) ? 0 : s[tid - 1];
    for (int i = st; i < en; i++) {
        int c = g_cnt[i];
        g_rowptr[i] = run;
        run += c;
        g_invdeg[i] = 1.0f / (float)(c > 1 ? c : 1);
        g_cnt[i] = 0;
    }
    if (tid == 0) g_rowptr[NN] = EE;
}

__global__ void fill_kernel(const int* __restrict__ src,
                            const int* __restrict__ dst) {
    int i = blockIdx.x * blockDim.x + threadIdx.x;
    if (i >= EE) return;
    int d = dst[i];
    int pos = g_rowptr[d] + atomicAdd(&g_cnt[d], 1);
    g_colidx[pos] = src[i];
}

__global__ void transW_kernel(const float* __restrict__ wl,
                              const float* __restrict__ wr) {
    int idx = blockIdx.x * blockDim.x + threadIdx.x;
    if (idx >= LL * 2 * HH * HH) return;
    int l = idx / (2 * HH * HH);
    int rem = idx % (2 * HH * HH);
    int k = rem / HH;
    int o = rem % HH;
    float v = (k < HH) ? wl[(l * HH + o) * HH + k]
                       : wr[(l * HH + o) * HH + (k - HH)];
    g_Wt[idx] = v;
}

// ---------------- per-layer kernels ----------------
// mean aggregation over RAW prev-layer y, with BN affine applied to the mean:
//   out = deg>0 ? a .* mean + b : 0
__global__ void agg_kernel(const float* __restrict__ x, int sel) {
    int t = blockIdx.x * blockDim.x + threadIdx.x;
    int node = t >> 5;
    int lane = t & 31;
    if (node >= NN) return;
    const float4* h4 = (const float4*)sel_h(x, sel);
    float4 acc = make_float4(0.f, 0.f, 0.f, 0.f);
    int e0 = g_rowptr[node];
    int e1 = g_rowptr[node + 1];
    for (int j = e0; j < e1; j++) {
        int s = g_colidx[j];
        float4 v = h4[s * 32 + lane];
        acc.x += v.x; acc.y += v.y; acc.z += v.z; acc.w += v.w;
    }
    float4 o;
    if (e1 > e0) {
        float inv = g_invdeg[node];
        float4 a = ((const float4*)g_coefA)[lane];
        float4 b = ((const float4*)g_coefB)[lane];
        o = make_float4(fmaf(a.x, acc.x * inv, b.x), fmaf(a.y, acc.y * inv, b.y),
                        fmaf(a.z, acc.z * inv, b.z), fmaf(a.w, acc.w * inv, b.w));
    } else {
        o = make_float4(0.f, 0.f, 0.f, 0.f);
    }
    ((float4*)g_agg)[node * 32 + lane] = o;
}

__global__ void zero_bn_kernel() {
    int c = threadIdx.x;
    g_sum[c] = 0.f;
    g_sumsq[c] = 0.f;
}

// fold current affine (coefA/coefB) into this layer's weights + bias:
//   Ws[k][o] = (k<128 ? 1 : a[k-128]) * Wt[l][k][o]
//   bias[o] += sum_k b[k] * Wr[o][k]
__global__ void prepareW_kernel(const float* __restrict__ bias, int layer) {
    int b = blockIdx.x, tid = threadIdx.x;
    if (b < 128) {
        int idx = b * 256 + tid;                 // 0..32767
        int k = idx >> 7;
        float s = (k < HH) ? 1.f : g_coefA[k - HH];
        g_Ws[idx] = s * g_Wt[layer * 2 * HH * HH + idx];
    } else if (tid < HH) {
        float s = bias[tid];
        const float* w = g_Wt + layer * 2 * HH * HH + HH * HH;  // Wr part [k][o]
        for (int k = 0; k < HH; k++) s += g_coefB[k] * w[k * HH + tid];
        g_bias[tid] = s;
    }
}

// y = relu(agg @ Wl^T + bias' + h_raw @ Wr_scaled^T), fused BN column sums.
// 128x128 tile / 256 threads / (4x2)x8 float2 acc per thread; K=256, 16 chunks.
__global__ void gemm_kernel(const float* __restrict__ x, int sel, int outsel) {
    __shared__ float As[16 * 128];   // A tile transposed: As[kk][row]
    __shared__ float Bs[16 * 128];   // W tile: Bs[kk][out]
    __shared__ float ssum[128];
    __shared__ float ssq[128];

    const int tid = threadIdx.x;
    const int tx = tid & 15;
    const int ty = tid >> 4;
    const int row0 = blockIdx.x * 128;

    const float* hin = sel_h(x, sel);
    float* yout = (outsel == 0) ? g_y0 : g_y1;

    float2 acc[4][8];   // row-pairs x 8 cols
    {
        float bc[8];
        #pragma unroll
        for (int j = 0; j < 4; j++) {
            bc[j]     = g_bias[tx * 4 + j];
            bc[4 + j] = g_bias[64 + tx * 4 + j];
        }
        #pragma unroll
        for (int i2 = 0; i2 < 4; i2++)
            #pragma unroll
            for (int j = 0; j < 8; j++) acc[i2][j] = make_float2(bc[j], bc[j]);
    }

    for (int chunk = 0; chunk < 16; chunk++) {
        {
            const float4* w4 = (const float4*)(g_Ws + chunk * 16 * HH);
            float4* bs4 = (float4*)Bs;
            #pragma unroll
            for (int i = tid; i < 512; i += 256) bs4[i] = w4[i];
        }
        {
            const float4* src4 = (const float4*)((chunk < 8) ? g_agg : hin);
            const int cseg = (chunk & 7) * 4;
            #pragma unroll
            for (int i = tid; i < 512; i += 256) {
                int r = i >> 2, seg = i & 3;
                int row = row0 + r;
                float4 v = make_float4(0.f, 0.f, 0.f, 0.f);
                if (row < NN) v = src4[row * 32 + cseg + seg];
                As[(seg * 4 + 0) * 128 + r] = v.x;
                As[(seg * 4 + 1) * 128 + r] = v.y;
                As[(seg * 4 + 2) * 128 + r] = v.z;
                As[(seg * 4 + 3) * 128 + r] = v.w;
            }
        }
        __syncthreads();
        #pragma unroll
        for (int kk = 0; kk < 16; kk++) {
            float4 a0 = *(const float4*)&As[kk * 128 + ty * 4];
            float4 a1 = *(const float4*)&As[kk * 128 + 64 + ty * 4];
            float4 b0 = *(const float4*)&Bs[kk * 128 + tx * 4];
            float4 b1 = *(const float4*)&Bs[kk * 128 + 64 + tx * 4];
            float2 ap[4] = {{a0.x, a0.y}, {a0.z, a0.w}, {a1.x, a1.y}, {a1.z, a1.w}};
            float  bj[8] = {b0.x, b0.y, b0.z, b0.w, b1.x, b1.y, b1.z, b1.w};
            #pragma unroll
            for (int j = 0; j < 8; j++) {
                float2 bb = make_float2(bj[j], bj[j]);
                #pragma unroll
                for (int i2 = 0; i2 < 4; i2++) ffma2(acc[i2][j], ap[i2], bb);
            }
        }
        __syncthreads();
    }

    // epilogue: relu, store, BN column sums
    float csum[8], csq[8];
    #pragma unroll
    for (int j = 0; j < 8; j++) { csum[j] = 0.f; csq[j] = 0.f; }
    #pragma unroll
    for (int i2 = 0; i2 < 4; i2++) {
        int rbase = (i2 < 2) ? (row0 + ty * 4 + i2 * 2)
                             : (row0 + 64 + ty * 4 + (i2 - 2) * 2);
        #pragma unroll
        for (int half = 0; half < 2; half++) {
            int r = rbase + half;
            if (r < NN) {
                float v[8];
                #pragma unroll
                for (int j = 0; j < 8; j++) {
                    float raw = half ? acc[i2][j].y : acc[i2][j].x;
                    v[j] = fmaxf(raw, 0.f);
                    csum[j] += v[j];
                    csq[j]  += v[j] * v[j];
                }
                float4* y4 = (float4*)(yout + r * HH);
                y4[tx]      = make_float4(v[0], v[1], v[2], v[3]);
                y4[16 + tx] = make_float4(v[4], v[5], v[6], v[7]);
            }
        }
    }
    if (tid < 128) { ssum[tid] = 0.f; ssq[tid] = 0.f; }
    __syncthreads();
    #pragma unroll
    for (int j = 0; j < 4; j++) {
        atomicAdd(&ssum[tx * 4 + j],      csum[j]);
        atomicAdd(&ssq[tx * 4 + j],       csq[j]);
        atomicAdd(&ssum[64 + tx * 4 + j], csum[4 + j]);
        atomicAdd(&ssq[64 + tx * 4 + j],  csq[4 + j]);
    }
    __syncthreads();
    if (tid < 128) {
        atomicAdd(&g_sum[tid],   ssum[tid]);
        atomicAdd(&g_sumsq[tid], ssq[tid]);
    }
}

__global__ void bn_finalize_kernel(const float* __restrict__ gamma,
                                   const float* __restrict__ beta) {
    int c = threadIdx.x;
    float mean = g_sum[c] / (float)NN;
    float var  = g_sumsq[c] / (float)NN - mean * mean;
    float a = gamma[c] * rsqrtf(var + BN_EPS);
    g_coefA[c] = a;
    g_coefB[c] = beta[c] - mean * a;
}

// fold last layer's affine into the FC: fcs = a .* fcw ; c0 = sum(b .* fcw)
__global__ void fcprep_kernel(const float* __restrict__ fcw) {
    __shared__ float red[128];
    int c = threadIdx.x;
    float w = fcw[c];
    g_fcs[c] = g_coefA[c] * w;
    red[c] = g_coefB[c] * w;
    __syncthreads();
    for (int off = 64; off; off >>= 1) {
        if (c < off) red[c] += red[c + off];
        __syncthreads();
    }
    if (c == 0) g_c0 = red[0];
}

// per-node dot with folded fc weights; + per-node constant c0
__global__ void pool_kernel(const int* __restrict__ batch) {
    int t = blockIdx.x * blockDim.x + threadIdx.x;
    int node = t >> 5;
    int lane = t & 31;
    if (node >= NN) return;
    float4 v = ((const float4*)g_y0)[node * 32 + lane];
    float4 w = ((const float4*)g_fcs)[lane];
    float s = v.x * w.x + v.y * w.y + v.z * w.z + v.w * w.w;
    #pragma unroll
    for (int off = 16; off; off >>= 1) s += __shfl_down_sync(0xffffffffu, s, off);
    if (lane == 0) atomicAdd(&g_pool[batch[node]], s + g_c0);
}

__global__ void final_kernel(const float* __restrict__ fcb, float* __restrict__ out) {
    int g = threadIdx.x;
    if (g < GG) {
        float z = g_pool[g] + fcb[0];
        out[g] = 1.0f / (1.0f + expf(-z));
    }
}

// ---------------- launch ----------------
extern "C" void kernel_launch(void* const* d_in, const int* in_sizes, int n_in,
                              void* d_out, int out_size) {
    const float* x       = (const float*)d_in[0];
    const int*   ei      = (const int*)d_in[1];
    const int*   src     = ei;
    const int*   dst     = ei + EE;
    const int*   batch   = (const int*)d_in[3];
    const float* lin_l_w = (const float*)d_in[4];
    const float* lin_l_b = (const float*)d_in[5];
    const float* lin_r_w = (const float*)d_in[6];
    const float* gamma   = (const float*)d_in[7];
    const float* beta    = (const float*)d_in[8];
    const float* fcw     = (const float*)d_in[9];
    const float* fcb     = (const float*)d_in[10];
    float*       out     = (float*)d_out;

    zero_init_kernel<<<(NN + 255) / 256, 256>>>();
    count_kernel<<<(EE + 255) / 256, 256>>>(dst);
    scan_kernel<<<1, 1024>>>();
    fill_kernel<<<(EE + 255) / 256, 256>>>(src, dst);
    transW_kernel<<<(LL * 2 * HH * HH + 255) / 256, 256>>>(lin_l_w, lin_r_w);

    for (int l = 0; l < LL; l++) {
        int sel    = (l == 0) ? 0 : ((l == 1) ? 1 : 2);   // x, g_y0, g_y1
        int outsel = (l == 1) ? 1 : 0;                    // y0, y1, y0
        agg_kernel<<<(NN * 32 + 255) / 256, 256>>>(x, sel);
        prepareW_kernel<<<129, 256>>>(lin_l_b + l * HH, l);
        zero_bn_kernel<<<1, 128>>>();
        gemm_kernel<<<(NN + 127) / 128, 256>>>(x, sel, outsel);
        bn_finalize_kernel<<<1, 128>>>(gamma + l * HH, beta + l * HH);
    }

    fcprep_kernel<<<1, 128>>>(fcw);
    pool_kernel<<<(NN * 32 + 255) / 256, 256>>>(batch);
    final_kernel<<<1, 64>>>(fcb, out);
}